// round 16
// baseline (speedup 1.0000x reference)
#include <cuda_runtime.h>
#include <cuda_fp16.h>
#include <cstdint>

#define E_MAX 100000
#define E_PAD 100096        // multiple of 128
#define M_MAX 300000
#define G_MAX 256

// ---------------- scratch (device globals; no allocations allowed) ----------
__device__ __align__(16) uint32_t g_Hhi[2][E_PAD * 32];
__device__ __align__(16) uint32_t g_Hlo[2][E_PAD * 32];
__device__ __align__(16) uint32_t g_AGGhi[2][E_PAD * 32];
__device__ __align__(16) uint32_t g_AGGlo[2][E_PAD * 32];
__device__ __align__(16) __half   g_PQh[2][E_PAD * 128];   // P[0,64) | Q[64,128)
__device__ int   g_cnt[E_MAX];
__device__ int   g_rowptr[E_MAX];
__device__ int   g_cursor[E_MAX];
__device__ int   g_csrf[M_MAX];
__device__ int   g_bsums[256];
__device__ int   g_gcnt[G_MAX];
__device__ int   g_grow[G_MAX];
__device__ int   g_gcur[G_MAX];
__device__ int   g_glist[E_MAX];
__device__ float g_pool[G_MAX * 123];
__device__ float g_h1[G_MAX * 256];
__device__ float g_h2[G_MAX * 256];
__device__ __align__(16) uint32_t g_Bw[2][256 * 64];   // GRU: [256 n][128 k]
__device__ __align__(16) uint32_t g_Pw[2][128 * 32];   // PQ:  [128 n][64 k]

// ---------------- helpers ---------------------------------------------------
__device__ __forceinline__ float seluf(float x) {
    const float sc = 1.0507009873554805f, al = 1.6732632423543772f;
    return x > 0.f ? sc * x : sc * al * (__expf(x) - 1.f);
}
__device__ __forceinline__ float sigm(float x) {
    return __fdividef(1.f, 1.f + __expf(-x));
}
__device__ __forceinline__ float tanha(float x) {
    return __fmaf_rn(2.f, sigm(x + x), -1.f);
}

__device__ __forceinline__ void mma16816(float* c, uint32_t a0, uint32_t a1,
                                         uint32_t a2, uint32_t a3,
                                         uint32_t b0, uint32_t b1) {
    asm volatile(
        "mma.sync.aligned.m16n8k16.row.col.f32.f16.f16.f32 "
        "{%0,%1,%2,%3}, {%4,%5,%6,%7}, {%8,%9}, {%0,%1,%2,%3};"
        : "+f"(c[0]), "+f"(c[1]), "+f"(c[2]), "+f"(c[3])
        : "r"(a0), "r"(a1), "r"(a2), "r"(a3), "r"(b0), "r"(b1));
}
__device__ __forceinline__ void ldsm4(uint32_t* r, uint32_t saddr) {
    asm volatile("ldmatrix.sync.aligned.m8n8.x4.shared.b16 {%0,%1,%2,%3}, [%4];"
                 : "=r"(r[0]), "=r"(r[1]), "=r"(r[2]), "=r"(r[3]) : "r"(saddr));
}
__device__ __forceinline__ void cpa16(uint32_t sdst, const void* gsrc) {
    asm volatile("cp.async.cg.shared.global [%0], [%1], 16;"
                 :: "r"(sdst), "l"(gsrc));
}
#define CP_WAIT() asm volatile("cp.async.commit_group;\ncp.async.wait_group 0;" ::: "memory")

__device__ __forceinline__ uint32_t pack_f16(float v0, float v1, uint32_t* lo) {
    __half h0 = __float2half(v0), h1 = __float2half(v1);
    __half l0 = __float2half(v0 - __half2float(h0));
    __half l1 = __float2half(v1 - __half2float(h1));
    *lo = ((uint32_t)__half_as_ushort(l1) << 16) | __half_as_ushort(l0);
    return ((uint32_t)__half_as_ushort(h1) << 16) | __half_as_ushort(h0);
}
__device__ __forceinline__ float f16lo(uint32_t w) {
    return __half2float(__ushort_as_half((unsigned short)(w & 0xFFFF)));
}
__device__ __forceinline__ float f16hi(uint32_t w) {
    return __half2float(__ushort_as_half((unsigned short)(w >> 16)));
}

// ---------------- weight image builders (device-side) ------------------------
__device__ __forceinline__ void buildB_one(int idx, const float* Wx,
                                           const float* Wh, int D, int set) {
    int n = idx >> 7, k = idx & 127;
    int ld3 = 3 * D;
    float v = 0.f;
    if (n < 128) {
        int g = n >> 6, c = n & 63;
        if (c < D) {
            if (k < 64) { if (k < D) v = Wx[k * ld3 + g * D + c]; }
            else { int kk = k - 64; if (kk < D) v = Wh[kk * ld3 + g * D + c]; }
        }
    } else if (n < 192) {
        int c = n - 128;
        if (c < D && k < 64 && k < D) v = Wx[k * ld3 + 2 * D + c];
    } else {
        int c = n - 192, kk = k - 64;
        if (c < D && k >= 64 && kk < D) v = Wh[kk * ld3 + 2 * D + c];
    }
    ((__half*)g_Bw[set])[idx] = __float2half(v);
}
__device__ __forceinline__ void buildP_one(int idx, const float* W, int D, int set) {
    int n = idx >> 6, k = idx & 63;
    float v = 0.f;
    if (k < D) {
        if (n < 64) { if (n < D) v = W[k * D + n]; }
        else { int c = n - 64; if (c < D) v = W[(D + k) * D + c]; }
    }
    ((__half*)g_Pw[set])[idx] = __float2half(v);
}

// ---------------- fused setup: pack states + weight images + zeroing ----------
__global__ void k_setup(const float* __restrict__ gsrc, const float* __restrict__ nsrc,
                        const float* __restrict__ Wx_e, const float* __restrict__ Wh_e,
                        const float* __restrict__ Wx_n, const float* __restrict__ Wh_n,
                        const float* __restrict__ W_msg, const float* __restrict__ W_nmsg,
                        int E, int G) {
    int i = blockIdx.x * blockDim.x + threadIdx.x;
    int o0 = E * 32;
    int o1 = o0 + E * 32;
    int o2 = o1 + 256 * 128;
    int o3 = o2 + 256 * 128;
    int o4 = o3 + 128 * 64;
    int o5 = o4 + 128 * 64;
    int o6 = o5 + E;
    int o7 = o6 + G;
    if (i < o0) {                      // edge state pack (D=64)
        int e = i >> 5, j = i & 31;
        float v0 = gsrc[e * 64 + 2 * j], v1 = gsrc[e * 64 + 2 * j + 1];
        uint32_t lo, hi = pack_f16(v0, v1, &lo);
        g_Hhi[0][i] = hi;
        g_Hlo[0][i] = lo;
    } else if (i < o1) {               // node state pack (D=59)
        int j2 = i - o0;
        int e = j2 >> 5, j = j2 & 31;
        int c0 = 2 * j, c1 = c0 + 1;
        float v0 = (c0 < 59) ? nsrc[e * 59 + c0] : 0.f;
        float v1 = (c1 < 59) ? nsrc[e * 59 + c1] : 0.f;
        uint32_t lo, hi = pack_f16(v0, v1, &lo);
        g_Hhi[1][j2] = hi;
        g_Hlo[1][j2] = lo;
    } else if (i < o2) buildB_one(i - o1, Wx_e, Wh_e, 64, 0);
    else if (i < o3) buildB_one(i - o2, Wx_n, Wh_n, 59, 1);
    else if (i < o4) buildP_one(i - o3, W_msg, 64, 0);
    else if (i < o5) buildP_one(i - o4, W_nmsg, 59, 1);
    else if (i < o6) g_cnt[i - o5] = 0;
    else if (i < o7) g_gcnt[i - o6] = 0;
}

// ---------------- CSR build ----------------------------------------------------
__global__ void k_hist2(const int* __restrict__ second, const int* __restrict__ gid,
                        int M, int E) {
    int i = blockIdx.x * blockDim.x + threadIdx.x;
    if (i < M) atomicAdd(&g_cnt[second[i]], 1);
    else if (i < M + E) atomicAdd(&g_gcnt[gid[i - M]], 1);
}
__global__ void k_scan1g(int E, int G, int nb) {
    __shared__ int s[1024];
    int t = threadIdx.x;
    if ((int)blockIdx.x == nb) {
        int v = (t < G) ? g_gcnt[t] : 0;
        s[t] = v;
        __syncthreads();
        for (int o = 1; o < 1024; o <<= 1) {
            int x = (t >= o) ? s[t - o] : 0;
            __syncthreads();
            s[t] += x;
            __syncthreads();
        }
        if (t < G) {
            int ex = s[t] - g_gcnt[t];
            g_grow[t] = ex;
            g_gcur[t] = ex;
        }
        return;
    }
    int i = blockIdx.x * 1024 + t;
    int v = (i < E) ? g_cnt[i] : 0;
    s[t] = v;
    __syncthreads();
    for (int o = 1; o < 1024; o <<= 1) {
        int x = (t >= o) ? s[t - o] : 0;
        __syncthreads();
        s[t] += x;
        __syncthreads();
    }
    if (i < E) g_rowptr[i] = s[t];
    if (t == 1023) g_bsums[blockIdx.x] = s[1023];
}
__global__ void k_scan2(int nb) {
    if (threadIdx.x == 0 && blockIdx.x == 0) {
        int run = 0;
        for (int b = 0; b < nb; b++) { int t = g_bsums[b]; g_bsums[b] = run; run += t; }
    }
}
__global__ void k_scan3(int E) {
    int i = blockIdx.x * blockDim.x + threadIdx.x;
    if (i < E) {
        int ex = g_rowptr[i] - g_cnt[i] + g_bsums[i / 1024];
        g_rowptr[i] = ex;
        g_cursor[i] = ex;
    }
}
__global__ void k_fill2(const int* __restrict__ first, const int* __restrict__ second,
                        const int* __restrict__ gid, int M, int E) {
    int i = blockIdx.x * blockDim.x + threadIdx.x;
    if (i < M) {
        int pos = atomicAdd(&g_cursor[second[i]], 1);
        g_csrf[pos] = first[i];
    } else if (i < M + E) {
        int e = i - M;
        int pos = atomicAdd(&g_gcur[gid[e]], 1);
        g_glist[pos] = e;
    }
}

// ---------------- dual message aggregation (fp16 PQ, half2 lanes) -------------
__global__ void k_agg2(int E, const float* __restrict__ b_e,
                       const float* __restrict__ b_n) {
    int w = (blockIdx.x * blockDim.x + threadIdx.x) >> 5;
    if (w >= 2 * E) return;
    int side = (w >= E) ? 1 : 0;
    int e = w - side * E;
    int D = side ? 59 : 64;
    const float* bias = side ? b_n : b_e;
    const __half2* PQ2 = (const __half2*)(g_PQh[side]);

    int lane = threadIdx.x & 31;
    int c0 = lane * 2, c1 = c0 + 1;
    float2 q = __half22float2(PQ2[(size_t)e * 64 + 32 + lane]);
    float q0 = q.x + ((c0 < D) ? bias[c0] : 0.f);
    float q1 = q.y + ((c1 < D) ? bias[c1] : 0.f);
    float a0 = 0.f, a1 = 0.f;
    int s = g_rowptr[e], n = g_cnt[e];
    int i = 0;
    for (; i + 2 <= n; i += 2) {
        int f0 = g_csrf[s + i], f1 = g_csrf[s + i + 1];
        float2 p0 = __half22float2(PQ2[(size_t)f0 * 64 + lane]);
        float2 p1 = __half22float2(PQ2[(size_t)f1 * 64 + lane]);
        a0 += seluf(p0.x + q0) + seluf(p1.x + q0);
        a1 += seluf(p0.y + q1) + seluf(p1.y + q1);
    }
    for (; i < n; i++) {
        int f = g_csrf[s + i];
        float2 p = __half22float2(PQ2[(size_t)f * 64 + lane]);
        a0 += seluf(p.x + q0);
        a1 += seluf(p.y + q1);
    }
    uint32_t lo, hi = pack_f16(a0, a1, &lo);
    g_AGGhi[side][(size_t)e * 32 + lane] = hi;
    g_AGGlo[side][(size_t)e * 32 + lane] = lo;
}

// ---------------- persistent fused iteration kernel ----------------------------
// Grid = 148 blocks; block b owns side b&1, strides tiles (128 rows) by 74.
// Weights (B, PB) + biases load ONCE per block; per tile only A streams in.
#define APITCH 68
#define BPITCH 36
#define SM_AHI 0
#define SM_ALO (128 * APITCH)
#define SM_B (2 * 128 * APITCH)
#define SM_PB (2 * 128 * APITCH + 256 * APITCH)
#define SM_BIAS (SM_PB + 128 * BPITCH)
#define SM_BYTES ((SM_BIAS + 256) * 4)

__global__ void __launch_bounds__(512, 1) k_iter(
        const float* __restrict__ bxe, const float* __restrict__ bhe,
        const float* __restrict__ bxn, const float* __restrict__ bhn,
        int E, int ntiles, int tstride, int mode, int do_pq) {
    extern __shared__ uint32_t sm[];
    float* fsm = (float*)sm;
    const int tid = threadIdx.x;
    const int wid = tid >> 5, lane = tid & 31;
    const int wrow = wid & 7, whalf = wid >> 3;
    const int gq = lane >> 2, tig = lane & 3;

    const int side = blockIdx.x & 1;
    const int tstart = blockIdx.x >> 1;
    const float* bx = side ? bxn : bxe;
    const float* bh = side ? bhn : bhe;
    const int D = side ? 59 : 64;
    uint32_t* Hh = g_Hhi[side];
    uint32_t* Hl = g_Hlo[side];
    const uint32_t* Ah = g_AGGhi[side];
    const uint32_t* Al = g_AGGlo[side];
    __half* PQh = g_PQh[side];

    const int mrow = wrow * 16;
    const uint32_t smb = (uint32_t)__cvta_generic_to_shared(sm);
    const int arow = mrow + ((lane >> 3) & 1) * 8 + (lane & 7);
    const int acol = (lane >> 4) * 4;
    const int brow = (lane >> 4) * 8 + (lane & 7);
    const int bcol = ((lane >> 3) & 1) * 4;

    // ---- hoisted weight/bias loads (once per block) ----
    if (mode == 0) {
        for (int idx = tid; idx < 256 * 16; idx += 512) {
            int n = idx >> 4, ch = (idx & 15) * 4;
            cpa16(smb + (uint32_t)(SM_B + n * APITCH + ch) * 4,
                  g_Bw[side] + n * 64 + ch);
        }
        if (tid < 64) {
            float bz = 0.f, br = 0.f, bxh = 0.f, bhh = 0.f;
            if (tid < D) {
                bz = bx[tid] + bh[tid];
                br = bx[D + tid] + bh[D + tid];
                bxh = bx[2 * D + tid];
                bhh = bh[2 * D + tid];
            }
            fsm[SM_BIAS + tid] = bz;
            fsm[SM_BIAS + 64 + tid] = br;
            fsm[SM_BIAS + 128 + tid] = bxh;
            fsm[SM_BIAS + 192 + tid] = bhh;
        }
    }
    if (mode == 1 || do_pq) {
        for (int idx = tid; idx < 128 * 8; idx += 512) {
            int n = idx >> 3, ch = (idx & 7) * 4;
            cpa16(smb + (uint32_t)(SM_PB + n * BPITCH + ch) * 4,
                  g_Pw[side] + n * 32 + ch);
        }
    }

    // ---- tile loop ----
    for (int t = tstart; t < ntiles; t += tstride) {
        const int row0 = t * 128;

        if (mode == 1) {
            for (int idx = tid; idx < 128 * 8; idx += 512) {
                int m = idx >> 3, ch = (idx & 7) * 4;
                size_t off = (size_t)(row0 + m) * 32 + ch;
                cpa16(smb + (uint32_t)(SM_AHI + m * APITCH + ch) * 4, Hh + off);
                cpa16(smb + (uint32_t)(SM_ALO + m * APITCH + ch) * 4, Hl + off);
            }
        } else {
            for (int idx = tid; idx < 128 * 8; idx += 512) {
                int m = idx >> 3, ch = (idx & 7) * 4;
                size_t off = (size_t)(row0 + m) * 32 + ch;
                cpa16(smb + (uint32_t)(SM_AHI + m * APITCH + ch) * 4, Ah + off);
                cpa16(smb + (uint32_t)(SM_ALO + m * APITCH + ch) * 4, Al + off);
                cpa16(smb + (uint32_t)(SM_AHI + m * APITCH + 32 + ch) * 4, Hh + off);
                cpa16(smb + (uint32_t)(SM_ALO + m * APITCH + 32 + ch) * 4, Hl + off);
            }
        }
        CP_WAIT();
        __syncthreads();

        if (mode == 0) {
            uint32_t stH[2][2][2], stL[2][2][2];

            for (int ci_i = 0; ci_i < 2; ci_i++) {
                int ci = whalf * 2 + ci_i;
                float acc[4][2][4] = {};

#pragma unroll
                for (int kt = 0; kt < 8; kt++) {
                    uint32_t ah[4], al[4];
                    ldsm4(ah, smb + (uint32_t)(SM_AHI + arow * APITCH + acol + kt * 8) * 4);
                    ldsm4(al, smb + (uint32_t)(SM_ALO + arow * APITCH + acol + kt * 8) * 4);
#pragma unroll
                    for (int g4 = 0; g4 < 4; g4++) {
                        uint32_t b[4];
                        ldsm4(b, smb + (uint32_t)(SM_B + (g4 * 64 + ci * 16 + brow) * APITCH +
                                                  bcol + kt * 8) * 4);
                        mma16816(acc[g4][0], ah[0], ah[1], ah[2], ah[3], b[0], b[1]);
                        mma16816(acc[g4][0], al[0], al[1], al[2], al[3], b[0], b[1]);
                        mma16816(acc[g4][1], ah[0], ah[1], ah[2], ah[3], b[2], b[3]);
                        mma16816(acc[g4][1], al[0], al[1], al[2], al[3], b[2], b[3]);
                    }
                }

                // GRU epilogue
#pragma unroll
                for (int nt = 0; nt < 2; nt++) {
#pragma unroll
                    for (int rh = 0; rh < 2; rh++) {
                        int m = mrow + gq + rh * 8;
                        int r = row0 + m;
                        int c0 = ci * 16 + nt * 8 + tig * 2;
                        int widx = c0 >> 1;
                        uint32_t hw = sm[SM_AHI + m * APITCH + 32 + widx];
                        uint32_t lw = sm[SM_ALO + m * APITCH + 32 + widx];

                        float hold0 = f16lo(hw) + f16lo(lw);
                        float z0 = sigm(acc[0][nt][rh * 2] + fsm[SM_BIAS + c0]);
                        float rr0 = sigm(acc[1][nt][rh * 2] + fsm[SM_BIAS + 64 + c0]);
                        float cand0 = tanha(acc[2][nt][rh * 2] + fsm[SM_BIAS + 128 + c0] +
                                            rr0 * (acc[3][nt][rh * 2] + fsm[SM_BIAS + 192 + c0]));
                        float h0 = z0 * hold0 + (1.f - z0) * cand0;

                        int c1 = c0 + 1;
                        float hold1 = f16hi(hw) + f16hi(lw);
                        float z1 = sigm(acc[0][nt][rh * 2 + 1] + fsm[SM_BIAS + c1]);
                        float rr1 = sigm(acc[1][nt][rh * 2 + 1] + fsm[SM_BIAS + 64 + c1]);
                        float cand1 = tanha(acc[2][nt][rh * 2 + 1] + fsm[SM_BIAS + 128 + c1] +
                                            rr1 * (acc[3][nt][rh * 2 + 1] + fsm[SM_BIAS + 192 + c1]));
                        float h1 = z1 * hold1 + (1.f - z1) * cand1;

                        uint32_t lo, hi = pack_f16(h0, h1, &lo);
                        size_t gw = (size_t)r * 32 + widx;
                        Hh[gw] = hi;
                        Hl[gw] = lo;
                        stH[ci_i][nt][rh] = hi;
                        stL[ci_i][nt][rh] = lo;
                    }
                }
            }

            if (do_pq) {
                __syncthreads();   // all warps done reading A/B for GRU

                // stash Hnew into A region (kp < 32)
#pragma unroll
                for (int ci_i = 0; ci_i < 2; ci_i++) {
                    int ci = whalf * 2 + ci_i;
#pragma unroll
                    for (int nt = 0; nt < 2; nt++) {
#pragma unroll
                        for (int rh = 0; rh < 2; rh++) {
                            int kp = ci * 8 + nt * 4 + tig;
                            int m = mrow + gq + rh * 8;
                            sm[SM_AHI + m * APITCH + kp] = stH[ci_i][nt][rh];
                            sm[SM_ALO + m * APITCH + kp] = stL[ci_i][nt][rh];
                        }
                    }
                }
                __syncthreads();
            }
        }

        if (mode == 1 || do_pq) {
            // ---- PQ mma: PQ[128 x 128] = A(kp<32) @ Bpq^T ----
            float acc2[8][4] = {};
#pragma unroll
            for (int kt = 0; kt < 4; kt++) {
                uint32_t ah[4], al[4];
                ldsm4(ah, smb + (uint32_t)(SM_AHI + arow * APITCH + acol + kt * 8) * 4);
                ldsm4(al, smb + (uint32_t)(SM_ALO + arow * APITCH + acol + kt * 8) * 4);
#pragma unroll
                for (int np = 0; np < 4; np++) {
                    uint32_t b[4];
                    ldsm4(b, smb + (uint32_t)(SM_PB + (whalf * 64 + np * 16 + brow) * BPITCH +
                                              bcol + kt * 8) * 4);
                    mma16816(acc2[np * 2], ah[0], ah[1], ah[2], ah[3], b[0], b[1]);
                    mma16816(acc2[np * 2], al[0], al[1], al[2], al[3], b[0], b[1]);
                    mma16816(acc2[np * 2 + 1], ah[0], ah[1], ah[2], ah[3], b[2], b[3]);
                    mma16816(acc2[np * 2 + 1], al[0], al[1], al[2], al[3], b[2], b[3]);
                }
            }

            int r0 = row0 + mrow + gq, r1 = r0 + 8;
#pragma unroll
            for (int nt2 = 0; nt2 < 8; nt2++) {
                int cb = whalf * 64 + nt2 * 8 + tig * 2;
                *(__half2*)&PQh[(size_t)r0 * 128 + cb] =
                    __floats2half2_rn(acc2[nt2][0], acc2[nt2][1]);
                *(__half2*)&PQh[(size_t)r1 * 128 + cb] =
                    __floats2half2_rn(acc2[nt2][2], acc2[nt2][3]);
            }
        }

        __syncthreads();   // A region reused next tile
    }
}

// ---------------- readout: 8-way parallel pooling -----------------------------
__global__ void __launch_bounds__(1024) k_pool2(int G) {
    __shared__ float red[8 * 128];
    int g = blockIdx.x;
    int grp = threadIdx.x >> 7;       // 0..7
    int c = threadIdx.x & 127;        // 0..127 (123 used)
    int s = g_grow[g], n = g_gcnt[g];
    float acc = 0.f;
    if (c < 123) {
        int side = (c < 64) ? 0 : 1;
        int cc = (c < 64) ? c : c - 64;
        int widx = cc >> 1, hiHalf = cc & 1;
        for (int j = grp; j < n; j += 8) {
            int e = g_glist[s + j];
            uint32_t hw = g_Hhi[side][(size_t)e * 32 + widx];
            uint32_t lw = g_Hlo[side][(size_t)e * 32 + widx];
            acc += hiHalf ? (f16hi(hw) + f16hi(lw)) : (f16lo(hw) + f16lo(lw));
        }
    }
    red[grp * 128 + c] = acc;
    __syncthreads();
    if (grp == 0 && c < 123) {
        float t = 0.f;
#pragma unroll
        for (int k = 0; k < 8; k++) t += red[k * 128 + c];
        g_pool[g * 123 + c] = t;
    }
}
__global__ void k_mlp(const float* __restrict__ in, int ldin, int K,
                      const float* __restrict__ W, const float* __restrict__ b,
                      int N, float* __restrict__ out, int ldout, int act) {
    __shared__ float s[256];
    int row = blockIdx.x;
    for (int k = threadIdx.x; k < K; k += blockDim.x) s[k] = in[row * ldin + k];
    __syncthreads();
    for (int t = threadIdx.x; t < N; t += blockDim.x) {
        float acc = b[t];
        for (int k = 0; k < K; k++) acc += s[k] * W[k * N + t];
        if (act) acc = seluf(acc);
        out[row * ldout + t] = acc;
    }
}

// ---------------- launch ------------------------------------------------------
extern "C" void kernel_launch(void* const* d_in, const int* in_sizes, int n_in,
                              void* d_out, int out_size) {
    int idx = 0;
    const float* graph_state = (const float*)d_in[idx++];
    const float* node_state  = (const float*)d_in[idx++];
    const int*   first       = (const int*)d_in[idx++];
    const int*   second      = (const int*)d_in[idx++];
    const int*   gids        = (const int*)d_in[idx++];
    if (idx < n_in && in_sizes[idx] == 1) idx++;   // scalar states_num_edges
    const float* W_msg  = (const float*)d_in[idx++];
    const float* b_msg  = (const float*)d_in[idx++];
    const float* Wx_e   = (const float*)d_in[idx++];
    const float* Wh_e   = (const float*)d_in[idx++];
    const float* bx_e   = (const float*)d_in[idx++];
    const float* bh_e   = (const float*)d_in[idx++];
    const float* W_nmsg = (const float*)d_in[idx++];
    const float* b_nmsg = (const float*)d_in[idx++];
    const float* Wx_n   = (const float*)d_in[idx++];
    const float* Wh_n   = (const float*)d_in[idx++];
    const float* bx_n   = (const float*)d_in[idx++];
    const float* bh_n   = (const float*)d_in[idx++];
    const float* W1     = (const float*)d_in[idx++];
    const float* b1     = (const float*)d_in[idx++];
    const float* W2     = (const float*)d_in[idx++];
    const float* b2     = (const float*)d_in[idx++];
    const float* W3     = (const float*)d_in[idx++];
    const float* b3     = (const float*)d_in[idx++];

    const int E = in_sizes[0] / 64;
    const int M = in_sizes[3];
    const int G = out_size;

    float *POOL, *H1, *H2;
    cudaGetSymbolAddress((void**)&POOL, g_pool);
    cudaGetSymbolAddress((void**)&H1, g_h1);
    cudaGetSymbolAddress((void**)&H2, g_h2);

    cudaFuncSetAttribute(k_iter, cudaFuncAttributeMaxDynamicSharedMemorySize,
                         SM_BYTES);

    const int T256 = 256;
    auto gs = [](int n, int b) { return (n + b - 1) / b; };
    const int ntiles = gs(E, 128);     // 782
    const int NB = 148;                // persistent blocks (1/SM)
    const int tstride = NB / 2;        // 74 blocks per side
    const int nb = gs(E, 1024);

    // L1: fused setup (state packing + weight images + zeroing)
    int total = E * 64 + 2 * 256 * 128 + 2 * 128 * 64 + E + G;
    k_setup<<<gs(total, T256), T256>>>(graph_state, node_state, Wx_e, Wh_e,
                                       Wx_n, Wh_n, W_msg, W_nmsg, E, G);
    // L2: histograms
    k_hist2<<<gs(M + E, T256), T256>>>(second, gids, M, E);
    // L3: block scans (edge CSR) + graph scan
    k_scan1g<<<nb + 1, 1024>>>(E, G, nb);
    // L4: initial PQ projection (persistent)
    k_iter<<<NB, 512, SM_BYTES>>>(bx_e, bh_e, bx_n, bh_n, E, ntiles, tstride, 1, 1);
    // L5-L7: finish CSR build
    k_scan2<<<1, 32>>>(nb);
    k_scan3<<<gs(E, T256), T256>>>(E);
    k_fill2<<<gs(M + E, T256), T256>>>(first, second, gids, M, E);

    // ---- dual message passing: T=4, edge+node in the same launches ----
    for (int t = 0; t < 4; t++) {
        k_agg2<<<gs(2 * E * 32, 256), 256>>>(E, b_msg, b_nmsg);
        k_iter<<<NB, 512, SM_BYTES>>>(bx_e, bh_e, bx_n, bh_n, E, ntiles, tstride,
                                      0, t < 3);
    }

    // ---- readout ----
    k_pool2<<<G, 1024>>>(G);
    k_mlp<<<G, 256>>>(POOL, 123, 123, W1, b1, 256, H1, 256, 1);
    k_mlp<<<G, 256>>>(H1, 256, 256, W2, b2, 256, H2, 256, 1);
    k_mlp<<<G, 256>>>(H2, 256, 256, W3, b3, 1, (float*)d_out, 1, 0);
}

// round 17
// speedup vs baseline: 1.0741x; 1.0741x over previous
#include <cuda_runtime.h>
#include <cuda_fp16.h>
#include <cstdint>

#define E_MAX 100000
#define E_PAD 100096        // covers ceil(E/64)*64 rows
#define M_MAX 300000
#define G_MAX 256

// ---------------- scratch (device globals; no allocations allowed) ----------
// states + aggregates stored as packed fp16 (hi,lo) words: word j = cols 2j,2j+1
__device__ __align__(16) uint32_t g_Hhi[2][E_PAD * 32];
__device__ __align__(16) uint32_t g_Hlo[2][E_PAD * 32];
__device__ __align__(16) uint32_t g_AGGhi[2][E_PAD * 32];
__device__ __align__(16) uint32_t g_AGGlo[2][E_PAD * 32];
__device__ __align__(16) __half   g_PQh[2][E_PAD * 128];   // P[0,64) | Q[64,128)
__device__ int   g_cnt[E_MAX];
__device__ int   g_rowptr[E_MAX];
__device__ int   g_cursor[E_MAX];
__device__ int   g_csrf[M_MAX];
__device__ int   g_bsums[256];
__device__ int   g_gcnt[G_MAX];
__device__ int   g_grow[G_MAX];
__device__ int   g_gcur[G_MAX];
__device__ int   g_glist[E_MAX];
__device__ float g_pool[G_MAX * 123];
__device__ float g_h1[G_MAX * 256];
__device__ float g_h2[G_MAX * 256];
// fp16 weight images (uint32-word views), 2 sets (edge/node)
__device__ __align__(16) uint32_t g_Bw[2][256 * 64];   // GRU: [256 n][128 k]
__device__ __align__(16) uint32_t g_Pw[2][128 * 32];   // PQ:  [128 n][64 k]

// ---------------- helpers ---------------------------------------------------
__device__ __forceinline__ float seluf(float x) {
    const float sc = 1.0507009873554805f, al = 1.6732632423543772f;
    return x > 0.f ? sc * x : sc * al * (__expf(x) - 1.f);
}
__device__ __forceinline__ float sigm(float x) {
    return __fdividef(1.f, 1.f + __expf(-x));
}
__device__ __forceinline__ float tanha(float x) {
    return __fmaf_rn(2.f, sigm(x + x), -1.f);
}

__device__ __forceinline__ void mma16816(float* c, uint32_t a0, uint32_t a1,
                                         uint32_t a2, uint32_t a3,
                                         uint32_t b0, uint32_t b1) {
    asm volatile(
        "mma.sync.aligned.m16n8k16.row.col.f32.f16.f16.f32 "
        "{%0,%1,%2,%3}, {%4,%5,%6,%7}, {%8,%9}, {%0,%1,%2,%3};"
        : "+f"(c[0]), "+f"(c[1]), "+f"(c[2]), "+f"(c[3])
        : "r"(a0), "r"(a1), "r"(a2), "r"(a3), "r"(b0), "r"(b1));
}
__device__ __forceinline__ void ldsm4(uint32_t* r, uint32_t saddr) {
    asm volatile("ldmatrix.sync.aligned.m8n8.x4.shared.b16 {%0,%1,%2,%3}, [%4];"
                 : "=r"(r[0]), "=r"(r[1]), "=r"(r[2]), "=r"(r[3]) : "r"(saddr));
}
__device__ __forceinline__ void cpa16(uint32_t sdst, const void* gsrc) {
    asm volatile("cp.async.cg.shared.global [%0], [%1], 16;"
                 :: "r"(sdst), "l"(gsrc));
}
#define CP_WAIT() asm volatile("cp.async.commit_group;\ncp.async.wait_group 0;" ::: "memory")

__device__ __forceinline__ uint32_t pack_f16(float v0, float v1, uint32_t* lo) {
    __half h0 = __float2half(v0), h1 = __float2half(v1);
    __half l0 = __float2half(v0 - __half2float(h0));
    __half l1 = __float2half(v1 - __half2float(h1));
    *lo = ((uint32_t)__half_as_ushort(l1) << 16) | __half_as_ushort(l0);
    return ((uint32_t)__half_as_ushort(h1) << 16) | __half_as_ushort(h0);
}
__device__ __forceinline__ float f16lo(uint32_t w) {
    return __half2float(__ushort_as_half((unsigned short)(w & 0xFFFF)));
}
__device__ __forceinline__ float f16hi(uint32_t w) {
    return __half2float(__ushort_as_half((unsigned short)(w >> 16)));
}

// ---------------- weight image builders (device-side) ------------------------
__device__ __forceinline__ void buildB_one(int idx, const float* Wx,
                                           const float* Wh, int D, int set) {
    int n = idx >> 7, k = idx & 127;
    int ld3 = 3 * D;
    float v = 0.f;
    if (n < 128) {
        int g = n >> 6, c = n & 63;
        if (c < D) {
            if (k < 64) { if (k < D) v = Wx[k * ld3 + g * D + c]; }
            else { int kk = k - 64; if (kk < D) v = Wh[kk * ld3 + g * D + c]; }
        }
    } else if (n < 192) {
        int c = n - 128;
        if (c < D && k < 64 && k < D) v = Wx[k * ld3 + 2 * D + c];
    } else {
        int c = n - 192, kk = k - 64;
        if (c < D && k >= 64 && kk < D) v = Wh[kk * ld3 + 2 * D + c];
    }
    ((__half*)g_Bw[set])[idx] = __float2half(v);
}
__device__ __forceinline__ void buildP_one(int idx, const float* W, int D, int set) {
    int n = idx >> 6, k = idx & 63;
    float v = 0.f;
    if (k < D) {
        if (n < 64) { if (n < D) v = W[k * D + n]; }
        else { int c = n - 64; if (c < D) v = W[(D + k) * D + c]; }
    }
    ((__half*)g_Pw[set])[idx] = __float2half(v);
}

// ---------------- fused setup: pack states + weight images + zeroing ----------
__global__ void k_setup(const float* __restrict__ gsrc, const float* __restrict__ nsrc,
                        const float* __restrict__ Wx_e, const float* __restrict__ Wh_e,
                        const float* __restrict__ Wx_n, const float* __restrict__ Wh_n,
                        const float* __restrict__ W_msg, const float* __restrict__ W_nmsg,
                        int E, int G) {
    int i = blockIdx.x * blockDim.x + threadIdx.x;
    int o0 = E * 32;
    int o1 = o0 + E * 32;
    int o2 = o1 + 256 * 128;
    int o3 = o2 + 256 * 128;
    int o4 = o3 + 128 * 64;
    int o5 = o4 + 128 * 64;
    int o6 = o5 + E;
    int o7 = o6 + G;
    if (i < o0) {                      // edge state pack (D=64)
        int e = i >> 5, j = i & 31;
        float v0 = gsrc[e * 64 + 2 * j], v1 = gsrc[e * 64 + 2 * j + 1];
        uint32_t lo, hi = pack_f16(v0, v1, &lo);
        g_Hhi[0][i] = hi;
        g_Hlo[0][i] = lo;
    } else if (i < o1) {               // node state pack (D=59)
        int j2 = i - o0;
        int e = j2 >> 5, j = j2 & 31;
        int c0 = 2 * j, c1 = c0 + 1;
        float v0 = (c0 < 59) ? nsrc[e * 59 + c0] : 0.f;
        float v1 = (c1 < 59) ? nsrc[e * 59 + c1] : 0.f;
        uint32_t lo, hi = pack_f16(v0, v1, &lo);
        g_Hhi[1][j2] = hi;
        g_Hlo[1][j2] = lo;
    } else if (i < o2) buildB_one(i - o1, Wx_e, Wh_e, 64, 0);
    else if (i < o3) buildB_one(i - o2, Wx_n, Wh_n, 59, 1);
    else if (i < o4) buildP_one(i - o3, W_msg, 64, 0);
    else if (i < o5) buildP_one(i - o4, W_nmsg, 59, 1);
    else if (i < o6) g_cnt[i - o5] = 0;
    else if (i < o7) g_gcnt[i - o6] = 0;
}

// ---------------- CSR build ----------------------------------------------------
__global__ void k_hist2(const int* __restrict__ second, const int* __restrict__ gid,
                        int M, int E) {
    int i = blockIdx.x * blockDim.x + threadIdx.x;
    if (i < M) atomicAdd(&g_cnt[second[i]], 1);
    else if (i < M + E) atomicAdd(&g_gcnt[gid[i - M]], 1);
}
__global__ void k_scan1g(int E, int G, int nb) {
    __shared__ int s[1024];
    int t = threadIdx.x;
    if ((int)blockIdx.x == nb) {
        int v = (t < G) ? g_gcnt[t] : 0;
        s[t] = v;
        __syncthreads();
        for (int o = 1; o < 1024; o <<= 1) {
            int x = (t >= o) ? s[t - o] : 0;
            __syncthreads();
            s[t] += x;
            __syncthreads();
        }
        if (t < G) {
            int ex = s[t] - g_gcnt[t];
            g_grow[t] = ex;
            g_gcur[t] = ex;
        }
        return;
    }
    int i = blockIdx.x * 1024 + t;
    int v = (i < E) ? g_cnt[i] : 0;
    s[t] = v;
    __syncthreads();
    for (int o = 1; o < 1024; o <<= 1) {
        int x = (t >= o) ? s[t - o] : 0;
        __syncthreads();
        s[t] += x;
        __syncthreads();
    }
    if (i < E) g_rowptr[i] = s[t];
    if (t == 1023) g_bsums[blockIdx.x] = s[1023];
}
__global__ void k_scan2(int nb) {
    if (threadIdx.x == 0 && blockIdx.x == 0) {
        int run = 0;
        for (int b = 0; b < nb; b++) { int t = g_bsums[b]; g_bsums[b] = run; run += t; }
    }
}
__global__ void k_scan3(int E) {
    int i = blockIdx.x * blockDim.x + threadIdx.x;
    if (i < E) {
        int ex = g_rowptr[i] - g_cnt[i] + g_bsums[i / 1024];
        g_rowptr[i] = ex;
        g_cursor[i] = ex;
    }
}
__global__ void k_fill2(const int* __restrict__ first, const int* __restrict__ second,
                        const int* __restrict__ gid, int M, int E) {
    int i = blockIdx.x * blockDim.x + threadIdx.x;
    if (i < M) {
        int pos = atomicAdd(&g_cursor[second[i]], 1);
        g_csrf[pos] = first[i];
    } else if (i < M + E) {
        int e = i - M;
        int pos = atomicAdd(&g_gcur[gid[e]], 1);
        g_glist[pos] = e;
    }
}

// ---------------- dual message aggregation (fp16 PQ, half2 lanes) -------------
__global__ void k_agg2(int E, const float* __restrict__ b_e,
                       const float* __restrict__ b_n) {
    int w = (blockIdx.x * blockDim.x + threadIdx.x) >> 5;
    if (w >= 2 * E) return;
    int side = (w >= E) ? 1 : 0;
    int e = w - side * E;
    int D = side ? 59 : 64;
    const float* bias = side ? b_n : b_e;
    const __half2* PQ2 = (const __half2*)(g_PQh[side]);

    int lane = threadIdx.x & 31;
    int c0 = lane * 2, c1 = c0 + 1;
    float2 q = __half22float2(PQ2[(size_t)e * 64 + 32 + lane]);
    float q0 = q.x + ((c0 < D) ? bias[c0] : 0.f);
    float q1 = q.y + ((c1 < D) ? bias[c1] : 0.f);
    float a0 = 0.f, a1 = 0.f;
    int s = g_rowptr[e], n = g_cnt[e];
    int i = 0;
    for (; i + 2 <= n; i += 2) {
        int f0 = g_csrf[s + i], f1 = g_csrf[s + i + 1];
        float2 p0 = __half22float2(PQ2[(size_t)f0 * 64 + lane]);
        float2 p1 = __half22float2(PQ2[(size_t)f1 * 64 + lane]);
        a0 += seluf(p0.x + q0) + seluf(p1.x + q0);
        a1 += seluf(p0.y + q1) + seluf(p1.y + q1);
    }
    for (; i < n; i++) {
        int f = g_csrf[s + i];
        float2 p = __half22float2(PQ2[(size_t)f * 64 + lane]);
        a0 += seluf(p.x + q0);
        a1 += seluf(p.y + q1);
    }
    uint32_t lo, hi = pack_f16(a0, a1, &lo);
    g_AGGhi[side][(size_t)e * 32 + lane] = hi;
    g_AGGlo[side][(size_t)e * 32 + lane] = lo;
}

// ---------------- fused dual iteration kernel (64 rows, 2 CTA/SM) --------------
#define APITCH 68
#define BPITCH 36
#define SM_AHI 0
#define SM_ALO (64 * APITCH)
#define SM_B (2 * 64 * APITCH)
#define SM_BIAS (SM_B + 256 * APITCH)
#define SM_BYTES ((SM_BIAS + 256) * 4)

__global__ void __launch_bounds__(256, 2) k_iter(
        const float* __restrict__ bxe, const float* __restrict__ bhe,
        const float* __restrict__ bxn, const float* __restrict__ bhn,
        int E, int rps, int mode, int do_pq) {
    extern __shared__ uint32_t sm[];
    float* fsm = (float*)sm;
    const int tid = threadIdx.x;
    const int wid = tid >> 5, lane = tid & 31;
    const int wrow = wid & 3, whalf = wid >> 2;
    const int gq = lane >> 2, tig = lane & 3;

    const int side = (blockIdx.x >= rps) ? 1 : 0;
    const int bid = blockIdx.x - side * rps;
    const float* bx = side ? bxn : bxe;
    const float* bh = side ? bhn : bhe;
    const int D = side ? 59 : 64;
    uint32_t* Hh = g_Hhi[side];
    uint32_t* Hl = g_Hlo[side];
    const uint32_t* Ah = g_AGGhi[side];
    const uint32_t* Al = g_AGGlo[side];
    __half* PQh = g_PQh[side];

    const int row0 = bid * 64;
    const int mrow = wrow * 16;

    const uint32_t smb = (uint32_t)__cvta_generic_to_shared(sm);
    const int arow = mrow + ((lane >> 3) & 1) * 8 + (lane & 7);
    const int acol = (lane >> 4) * 4;
    const int brow = (lane >> 4) * 8 + (lane & 7);
    const int bcol = ((lane >> 3) & 1) * 4;

    if (mode == 1) {
        // A (kp 0..31) = packed state (hi only — PQ GEMM is single-pass);
        // PB image into SM_B
        for (int idx = tid; idx < 64 * 8; idx += 256) {
            int m = idx >> 3, ch = (idx & 7) * 4;
            size_t off = (size_t)(row0 + m) * 32 + ch;
            cpa16(smb + (uint32_t)(SM_AHI + m * APITCH + ch) * 4, Hh + off);
        }
        for (int idx = tid; idx < 128 * 8; idx += 256) {
            int n = idx >> 3, ch = (idx & 7) * 4;
            cpa16(smb + (uint32_t)(SM_B + n * BPITCH + ch) * 4,
                  g_Pw[side] + n * 32 + ch);
        }
        CP_WAIT();
        __syncthreads();
    } else {
        // A = [agg | H] packed, all via cp.async; B = GRU weight image
        for (int idx = tid; idx < 64 * 8; idx += 256) {
            int m = idx >> 3, ch = (idx & 7) * 4;
            size_t off = (size_t)(row0 + m) * 32 + ch;
            cpa16(smb + (uint32_t)(SM_AHI + m * APITCH + ch) * 4, Ah + off);
            cpa16(smb + (uint32_t)(SM_ALO + m * APITCH + ch) * 4, Al + off);
            cpa16(smb + (uint32_t)(SM_AHI + m * APITCH + 32 + ch) * 4, Hh + off);
            cpa16(smb + (uint32_t)(SM_ALO + m * APITCH + 32 + ch) * 4, Hl + off);
        }
        for (int idx = tid; idx < 256 * 16; idx += 256) {
            int n = idx >> 4, ch = (idx & 15) * 4;
            cpa16(smb + (uint32_t)(SM_B + n * APITCH + ch) * 4,
                  g_Bw[side] + n * 64 + ch);
        }
        if (tid < 64) {
            float bz = 0.f, br = 0.f, bxh = 0.f, bhh = 0.f;
            if (tid < D) {
                bz = bx[tid] + bh[tid];
                br = bx[D + tid] + bh[D + tid];
                bxh = bx[2 * D + tid];
                bhh = bh[2 * D + tid];
            }
            fsm[SM_BIAS + tid] = bz;
            fsm[SM_BIAS + 64 + tid] = br;
            fsm[SM_BIAS + 128 + tid] = bxh;
            fsm[SM_BIAS + 192 + tid] = bhh;
        }
        CP_WAIT();
        __syncthreads();

        uint32_t stH[2][2][2];   // [ci_i][nt][rh] (hi only; PQ is single-pass)

        for (int ci_i = 0; ci_i < 2; ci_i++) {
            int ci = whalf * 2 + ci_i;
            float acc[4][2][4] = {};

#pragma unroll
            for (int kt = 0; kt < 8; kt++) {
                uint32_t ah[4], al[4];
                ldsm4(ah, smb + (uint32_t)(SM_AHI + arow * APITCH + acol + kt * 8) * 4);
                ldsm4(al, smb + (uint32_t)(SM_ALO + arow * APITCH + acol + kt * 8) * 4);
#pragma unroll
                for (int g4 = 0; g4 < 4; g4++) {
                    uint32_t b[4];
                    ldsm4(b, smb + (uint32_t)(SM_B + (g4 * 64 + ci * 16 + brow) * APITCH +
                                              bcol + kt * 8) * 4);
                    mma16816(acc[g4][0], ah[0], ah[1], ah[2], ah[3], b[0], b[1]);
                    mma16816(acc[g4][0], al[0], al[1], al[2], al[3], b[0], b[1]);
                    mma16816(acc[g4][1], ah[0], ah[1], ah[2], ah[3], b[2], b[3]);
                    mma16816(acc[g4][1], al[0], al[1], al[2], al[3], b[2], b[3]);
                }
            }

            // GRU epilogue: h_old from staged smem (hi+lo), fast transcendentals
#pragma unroll
            for (int nt = 0; nt < 2; nt++) {
#pragma unroll
                for (int rh = 0; rh < 2; rh++) {
                    int m = mrow + gq + rh * 8;
                    int r = row0 + m;
                    int c0 = ci * 16 + nt * 8 + tig * 2;
                    int widx = c0 >> 1;
                    uint32_t hw = sm[SM_AHI + m * APITCH + 32 + widx];
                    uint32_t lw = sm[SM_ALO + m * APITCH + 32 + widx];

                    float hold0 = f16lo(hw) + f16lo(lw);
                    float z0 = sigm(acc[0][nt][rh * 2] + fsm[SM_BIAS + c0]);
                    float rr0 = sigm(acc[1][nt][rh * 2] + fsm[SM_BIAS + 64 + c0]);
                    float cand0 = tanha(acc[2][nt][rh * 2] + fsm[SM_BIAS + 128 + c0] +
                                        rr0 * (acc[3][nt][rh * 2] + fsm[SM_BIAS + 192 + c0]));
                    float h0 = z0 * hold0 + (1.f - z0) * cand0;

                    int c1 = c0 + 1;
                    float hold1 = f16hi(hw) + f16hi(lw);
                    float z1 = sigm(acc[0][nt][rh * 2 + 1] + fsm[SM_BIAS + c1]);
                    float rr1 = sigm(acc[1][nt][rh * 2 + 1] + fsm[SM_BIAS + 64 + c1]);
                    float cand1 = tanha(acc[2][nt][rh * 2 + 1] + fsm[SM_BIAS + 128 + c1] +
                                        rr1 * (acc[3][nt][rh * 2 + 1] + fsm[SM_BIAS + 192 + c1]));
                    float h1 = z1 * hold1 + (1.f - z1) * cand1;

                    uint32_t lo, hi = pack_f16(h0, h1, &lo);
                    size_t gw = (size_t)r * 32 + widx;
                    Hh[gw] = hi;
                    Hl[gw] = lo;
                    stH[ci_i][nt][rh] = hi;
                }
            }
        }

        if (!do_pq) return;
        __syncthreads();   // all warps done reading A/B for GRU

        // stash Hnew (hi) into A region (kp < 32); overwrite B with PQ weights
#pragma unroll
        for (int ci_i = 0; ci_i < 2; ci_i++) {
            int ci = whalf * 2 + ci_i;
#pragma unroll
            for (int nt = 0; nt < 2; nt++) {
#pragma unroll
                for (int rh = 0; rh < 2; rh++) {
                    int kp = ci * 8 + nt * 4 + tig;
                    int m = mrow + gq + rh * 8;
                    sm[SM_AHI + m * APITCH + kp] = stH[ci_i][nt][rh];
                }
            }
        }
        for (int idx = tid; idx < 128 * 8; idx += 256) {
            int n = idx >> 3, ch = (idx & 7) * 4;
            cpa16(smb + (uint32_t)(SM_B + n * BPITCH + ch) * 4,
                  g_Pw[side] + n * 32 + ch);
        }
        CP_WAIT();
        __syncthreads();
    }

    // ---- PQ mma (single-pass, A-hi only): PQ[64 x 128] = A_hi(kp<32) @ Bpq^T --
    float acc2[8][4] = {};
#pragma unroll
    for (int kt = 0; kt < 4; kt++) {
        uint32_t ah[4];
        ldsm4(ah, smb + (uint32_t)(SM_AHI + arow * APITCH + acol + kt * 8) * 4);
#pragma unroll
        for (int np = 0; np < 4; np++) {
            uint32_t b[4];
            ldsm4(b, smb + (uint32_t)(SM_B + (whalf * 64 + np * 16 + brow) * BPITCH +
                                      bcol + kt * 8) * 4);
            mma16816(acc2[np * 2], ah[0], ah[1], ah[2], ah[3], b[0], b[1]);
            mma16816(acc2[np * 2 + 1], ah[0], ah[1], ah[2], ah[3], b[2], b[3]);
        }
    }

    int r0 = row0 + mrow + gq, r1 = r0 + 8;
#pragma unroll
    for (int nt2 = 0; nt2 < 8; nt2++) {
        int cb = whalf * 64 + nt2 * 8 + tig * 2;
        *(__half2*)&PQh[(size_t)r0 * 128 + cb] = __floats2half2_rn(acc2[nt2][0], acc2[nt2][1]);
        *(__half2*)&PQh[(size_t)r1 * 128 + cb] = __floats2half2_rn(acc2[nt2][2], acc2[nt2][3]);
    }
}

// ---------------- readout: 8-way parallel pooling -----------------------------
__global__ void __launch_bounds__(1024) k_pool2(int G) {
    __shared__ float red[8 * 128];
    int g = blockIdx.x;
    int grp = threadIdx.x >> 7;       // 0..7
    int c = threadIdx.x & 127;        // 0..127 (123 used)
    int s = g_grow[g], n = g_gcnt[g];
    float acc = 0.f;
    if (c < 123) {
        int side = (c < 64) ? 0 : 1;
        int cc = (c < 64) ? c : c - 64;
        int widx = cc >> 1, hiHalf = cc & 1;
        for (int j = grp; j < n; j += 8) {
            int e = g_glist[s + j];
            uint32_t hw = g_Hhi[side][(size_t)e * 32 + widx];
            uint32_t lw = g_Hlo[side][(size_t)e * 32 + widx];
            acc += hiHalf ? (f16hi(hw) + f16hi(lw)) : (f16lo(hw) + f16lo(lw));
        }
    }
    red[grp * 128 + c] = acc;
    __syncthreads();
    if (grp == 0 && c < 123) {
        float t = 0.f;
#pragma unroll
        for (int k = 0; k < 8; k++) t += red[k * 128 + c];
        g_pool[g * 123 + c] = t;
    }
}
__global__ void k_mlp(const float* __restrict__ in, int ldin, int K,
                      const float* __restrict__ W, const float* __restrict__ b,
                      int N, float* __restrict__ out, int ldout, int act) {
    __shared__ float s[256];
    int row = blockIdx.x;
    for (int k = threadIdx.x; k < K; k += blockDim.x) s[k] = in[row * ldin + k];
    __syncthreads();
    for (int t = threadIdx.x; t < N; t += blockDim.x) {
        float acc = b[t];
        for (int k = 0; k < K; k++) acc += s[k] * W[k * N + t];
        if (act) acc = seluf(acc);
        out[row * ldout + t] = acc;
    }
}

// ---------------- launch ------------------------------------------------------
extern "C" void kernel_launch(void* const* d_in, const int* in_sizes, int n_in,
                              void* d_out, int out_size) {
    int idx = 0;
    const float* graph_state = (const float*)d_in[idx++];
    const float* node_state  = (const float*)d_in[idx++];
    const int*   first       = (const int*)d_in[idx++];
    const int*   second      = (const int*)d_in[idx++];
    const int*   gids        = (const int*)d_in[idx++];
    if (idx < n_in && in_sizes[idx] == 1) idx++;   // scalar states_num_edges
    const float* W_msg  = (const float*)d_in[idx++];
    const float* b_msg  = (const float*)d_in[idx++];
    const float* Wx_e   = (const float*)d_in[idx++];
    const float* Wh_e   = (const float*)d_in[idx++];
    const float* bx_e   = (const float*)d_in[idx++];
    const float* bh_e   = (const float*)d_in[idx++];
    const float* W_nmsg = (const float*)d_in[idx++];
    const float* b_nmsg = (const float*)d_in[idx++];
    const float* Wx_n   = (const float*)d_in[idx++];
    const float* Wh_n   = (const float*)d_in[idx++];
    const float* bx_n   = (const float*)d_in[idx++];
    const float* bh_n   = (const float*)d_in[idx++];
    const float* W1     = (const float*)d_in[idx++];
    const float* b1     = (const float*)d_in[idx++];
    const float* W2     = (const float*)d_in[idx++];
    const float* b2     = (const float*)d_in[idx++];
    const float* W3     = (const float*)d_in[idx++];
    const float* b3     = (const float*)d_in[idx++];

    const int E = in_sizes[0] / 64;
    const int M = in_sizes[3];
    const int G = out_size;

    float *POOL, *H1, *H2;
    cudaGetSymbolAddress((void**)&POOL, g_pool);
    cudaGetSymbolAddress((void**)&H1, g_h1);
    cudaGetSymbolAddress((void**)&H2, g_h2);

    cudaFuncSetAttribute(k_iter, cudaFuncAttributeMaxDynamicSharedMemorySize,
                         SM_BYTES);

    const int T256 = 256;
    auto gs = [](int n, int b) { return (n + b - 1) / b; };
    const int rps = gs(E, 64);
    const int nb = gs(E, 1024);

    // L1: fused setup (state packing + weight images + zeroing)
    int total = E * 64 + 2 * 256 * 128 + 2 * 128 * 64 + E + G;
    k_setup<<<gs(total, T256), T256>>>(graph_state, node_state, Wx_e, Wh_e,
                                       Wx_n, Wh_n, W_msg, W_nmsg, E, G);
    // L2: histograms
    k_hist2<<<gs(M + E, T256), T256>>>(second, gids, M, E);
    // L3: block scans (edge CSR) + graph scan
    k_scan1g<<<nb + 1, 1024>>>(E, G, nb);
    // L4: initial PQ projection
    k_iter<<<2 * rps, 256, SM_BYTES>>>(bx_e, bh_e, bx_n, bh_n, E, rps, 1, 1);
    // L5-L7: finish CSR build
    k_scan2<<<1, 32>>>(nb);
    k_scan3<<<gs(E, T256), T256>>>(E);
    k_fill2<<<gs(M + E, T256), T256>>>(first, second, gids, M, E);

    // ---- dual message passing: T=4, edge+node in the same launches ----
    for (int t = 0; t < 4; t++) {
        k_agg2<<<gs(2 * E * 32, 256), 256>>>(E, b_msg, b_nmsg);
        k_iter<<<2 * rps, 256, SM_BYTES>>>(bx_e, bh_e, bx_n, bh_n, E, rps, 0, t < 3);
    }

    // ---- readout ----
    k_pool2<<<G, 1024>>>(G);
    k_mlp<<<G, 256>>>(POOL, 123, 123, W1, b1, 256, H1, 256, 1);
    k_mlp<<<G, 256>>>(H1, 256, 256, W2, b2, 256, H2, 256, 1);
    k_mlp<<<G, 256>>>(H2, 256, 256, W3, b3, 1, (float*)d_out, 1, 0);
}